// round 6
// baseline (speedup 1.0000x reference)
#include <cuda_runtime.h>
#include <math.h>

// ---------------------------------------------------------------------------
// WavetableSynth: B=16, L=48000, W=64, LWT=512
// Ref cumsum = XLA ReduceWindowRewriter(base=16) CPU pipeline (bit-matched R5):
//   reshape [3000,16]; inner sequential fold per 16-row (init 0)
//   row sums scanned recursively: 3000 -> 188 -> 12 -> direct sequential
//   unwind: one f32 add per level
// ---------------------------------------------------------------------------

#define BATCH 16
#define LEN   48000
#define NW    64
#define LWT   512
#define BL    (BATCH * LEN)          // 768000

#define INCF  0.032f                 // f32(512/16000)

#define NR0   3000                   // LEN/16
#define NR1   188                    // ceil(3000/16)
#define NR2   12                     // ceil(188/16)

__device__ float g_index[BL];        // final index per element

// ---------------------------------------------------------------------------
// Fused scan: one block per batch. Row sums + pyramid + index emit, all SMEM.
// Arithmetic order identical to the R5 k1/k2/k3 chain (bit-exact).
// ---------------------------------------------------------------------------
__global__ __launch_bounds__(256, 1)
void scan_all(const float* __restrict__ pitch)
{
    __shared__ float s0[NR0];          // level-0 row sums (3000)
    __shared__ float in1[NR1 * 16];    // level-1 inner prefixes (3008)
    __shared__ float in2[NR2 * 16];    // level-2 inner prefixes (192)
    __shared__ float S3[NR2];          // level-3 inclusive scan (12)
    __shared__ float S2[NR1];          // level-2 inclusive values (188)
    __shared__ float E1[NR0];          // exclusive offsets for level-0 rows

    const int b = blockIdx.x;
    const int t = threadIdx.x;

    // ---- phase 0: row sums (identical fold order to k1) ----
    for (int r = t; r < NR0; r += 256) {
        const float4* __restrict__ p4 = (const float4*)(pitch + b * LEN + r * 16);
        float acc = 0.0f;
#pragma unroll
        for (int q = 0; q < 4; q++) {
            float4 v = p4[q];
            acc = __fadd_rn(acc, __fmul_rn(INCF, v.x));
            acc = __fadd_rn(acc, __fmul_rn(INCF, v.y));
            acc = __fadd_rn(acc, __fmul_rn(INCF, v.z));
            acc = __fadd_rn(acc, __fmul_rn(INCF, v.w));
        }
        s0[r] = acc;
    }
    __syncthreads();

    // ---- level-1 inner folds: 188 rows of 16 (pad zeros beyond 3000) ----
    if (t < NR1) {
        float acc = 0.0f;
        for (int k = 0; k < 16; k++) {
            int idx = t * 16 + k;
            float v = (idx < NR0) ? s0[idx] : 0.0f;
            acc = __fadd_rn(acc, v);
            in1[t * 16 + k] = acc;
        }
    }
    __syncthreads();

    // ---- level-2 inner folds: 12 rows of 16 over 188 level-1 sums ----
    if (t < NR2) {
        float acc = 0.0f;
        for (int k = 0; k < 16; k++) {
            int m = t * 16 + k;
            float v = (m < NR1) ? in1[m * 16 + 15] : 0.0f;
            acc = __fadd_rn(acc, v);
            in2[t * 16 + k] = acc;
        }
    }
    __syncthreads();

    // ---- level-3 direct sequential scan of the 12 level-2 sums ----
    if (t == 0) {
        float run = 0.0f;
        for (int r = 0; r < NR2; r++) {
            run = __fadd_rn(run, in2[r * 16 + 15]);
            S3[r] = run;
        }
    }
    __syncthreads();

    // ---- level-2 inclusive values ----
    if (t < NR1) {
        int q = t >> 4;
        float e3 = (q == 0) ? 0.0f : S3[q - 1];
        S2[t] = __fadd_rn(in2[t], e3);
    }
    __syncthreads();

    // ---- level-1 exclusive offsets for level-0 rows ----
    for (int r = t; r < NR0; r += 256) {
        float e1;
        if (r == 0) {
            e1 = 0.0f;
        } else {
            int m = r - 1;
            int q = m >> 4;
            float e2 = (q == 0) ? 0.0f : S2[q - 1];
            e1 = __fadd_rn(in1[m], e2);
        }
        E1[r] = e1;
    }
    __syncthreads();

    // ---- emit final index (identical order to k3) ----
    for (int r = t; r < NR0; r += 256) {
        const float4* __restrict__ pb = (const float4*)(pitch + b * LEN + r * 16);
        const float4* __restrict__ p0 = (const float4*)(pitch + r * 16);
        float4* __restrict__ o4 = (float4*)(g_index + b * LEN + r * 16);
        const float e1 = E1[r];
        float acc = 0.0f;
#pragma unroll
        for (int q = 0; q < 4; q++) {
            float4 v = pb[q];
            float4 z = p0[q];
            float vv[4] = {v.x, v.y, v.z, v.w};
            float zz[4] = {z.x, z.y, z.z, z.w};
            float out[4];
#pragma unroll
            for (int k = 0; k < 4; k++) {
                acc = __fadd_rn(acc, __fmul_rn(INCF, vv[k]));
                float S0 = __fadd_rn(acc, e1);
                float x  = __fsub_rn(S0, __fmul_rn(INCF, zz[k]));
                float rr = fmodf(x, 512.0f);
                if (rr < 0.0f) rr = __fadd_rn(rr, 512.0f);
                if (__fsub_rn(512.0f, rr) < 1e-5f) rr = 0.0f;
                out[k] = rr;
            }
            o4[q] = make_float4(out[0], out[1], out[2], out[3]);
        }
    }
}

// ---------------------------------------------------------------------------
// Synth: HALF-WARP per element. Lanes 0-15 -> element 2p, lanes 16-31 -> 2p+1.
// Each lane covers 4 wavetables via float4 LDS (layout [pos][64], phase-
// conflict-free). 4 shfl_xor (8,4,2,1) reduce both halves simultaneously.
// ---------------------------------------------------------------------------
#define SYNTH_SMEM_BYTES (LWT * NW * 4)   // 131072
#define NPAIRS (BL / 2)                   // 384000

__device__ __forceinline__ float synth_pair_lane(
    float r, float4 a, const float4* __restrict__ wt4, int hl)
{
    float fl = floorf(r);
    int   il = (int)fl;
    float al = r - fl;
    int   ih = (int)ceilf(r);
    if (ih >= LWT) ih = 0;
    float4 lo = wt4[(il << 4) + hl];
    float4 hi = wt4[(ih << 4) + hl];
    float w0 = lo.x + al * (hi.x - lo.x);
    float w1 = lo.y + al * (hi.y - lo.y);
    float w2 = lo.z + al * (hi.z - lo.z);
    float w3 = lo.w + al * (hi.w - lo.w);
    float v = w0 * a.x;
    v = fmaf(w1, a.y, v);
    v = fmaf(w2, a.z, v);
    v = fmaf(w3, a.w, v);
    return v;
}

__device__ __forceinline__ float half_sum(float v)
{
#pragma unroll
    for (int off = 8; off > 0; off >>= 1)
        v += __shfl_xor_sync(0xffffffffu, v, off);
    return v;
}

__global__ __launch_bounds__(1024, 1)
void synth_kernel(const float* __restrict__ env,
                  const float* __restrict__ att,
                  const float* __restrict__ wtab,
                  float* __restrict__ out)
{
    extern __shared__ float wt[];   // [512][64] transposed
    for (int i = threadIdx.x; i < NW * LWT; i += 1024) {
        int w = i >> 9;
        int j = i & (LWT - 1);
        wt[j * NW + w] = wtab[i];
    }
    __syncthreads();

    const float4* __restrict__ wt4  = (const float4*)wt;
    const float4* __restrict__ att4 = (const float4*)att;

    const int lane = threadIdx.x & 31;
    const int half = lane >> 4;             // 0 or 1
    const int hl   = lane & 15;             // half-lane 0..15
    const int warp = (blockIdx.x << 5) + (threadIdx.x >> 5);
    const int nw   = gridDim.x << 5;

    int p = warp;
    for (; p + 3 * nw < NPAIRS; p += 4 * nw) {
        int me0 = 2 * p + half;
        int me1 = 2 * (p + nw) + half;
        int me2 = 2 * (p + 2 * nw) + half;
        int me3 = 2 * (p + 3 * nw) + half;

        // batch long-latency loads (MLP)
        float r0 = __ldg(&g_index[me0]);
        float r1 = __ldg(&g_index[me1]);
        float r2 = __ldg(&g_index[me2]);
        float r3 = __ldg(&g_index[me3]);
        float4 a0 = att4[me0 * 16 + hl];
        float4 a1 = att4[me1 * 16 + hl];
        float4 a2 = att4[me2 * 16 + hl];
        float4 a3 = att4[me3 * 16 + hl];
        float ev0 = __ldg(&env[me0]);
        float ev1 = __ldg(&env[me1]);
        float ev2 = __ldg(&env[me2]);
        float ev3 = __ldg(&env[me3]);

        float v0 = synth_pair_lane(r0, a0, wt4, hl);
        float v1 = synth_pair_lane(r1, a1, wt4, hl);
        float v2 = synth_pair_lane(r2, a2, wt4, hl);
        float v3 = synth_pair_lane(r3, a3, wt4, hl);

        v0 = half_sum(v0);
        v1 = half_sum(v1);
        v2 = half_sum(v2);
        v3 = half_sum(v3);

        if (hl == 0) {
            out[me0] = v0 * ev0;
            out[me1] = v1 * ev1;
            out[me2] = v2 * ev2;
            out[me3] = v3 * ev3;
        }
    }
    for (; p < NPAIRS; p += nw) {
        int me = 2 * p + half;
        float r  = __ldg(&g_index[me]);
        float4 a = att4[me * 16 + hl];
        float ev = __ldg(&env[me]);
        float v = half_sum(synth_pair_lane(r, a, wt4, hl));
        if (hl == 0) out[me] = v * ev;
    }
}

// ---------------------------------------------------------------------------
extern "C" void kernel_launch(void* const* d_in, const int* in_sizes, int n_in,
                              void* d_out, int out_size)
{
    const float* pitch = (const float*)d_in[0];
    const float* env   = (const float*)d_in[1];
    const float* att   = (const float*)d_in[2];
    const float* wtab  = (const float*)d_in[3];
    float* out = (float*)d_out;

    cudaFuncSetAttribute(synth_kernel,
        cudaFuncAttributeMaxDynamicSharedMemorySize, SYNTH_SMEM_BYTES);

    int nsm = 148;
    cudaDeviceGetAttribute(&nsm, cudaDevAttrMultiProcessorCount, 0);

    scan_all<<<BATCH, 256>>>(pitch);
    synth_kernel<<<nsm, 1024, SYNTH_SMEM_BYTES>>>(env, att, wtab, out);
}

// round 10
// speedup vs baseline: 1.3515x; 1.3515x over previous
#include <cuda_runtime.h>
#include <math.h>

// ---------------------------------------------------------------------------
// WavetableSynth: B=16, L=48000, W=64, LWT=512
// Ref cumsum = XLA ReduceWindowRewriter(base=16) CPU pipeline (bit-matched R5):
//   reshape [3000,16]; inner sequential fold per 16-row (init 0)
//   row sums scanned recursively: 3000 -> 188 -> 12 -> direct sequential
//   unwind: one f32 add per level
// Scan = R5 three-kernel chain (parallel).  Synth = R6 half-warp kernel.
// ---------------------------------------------------------------------------

#define BATCH 16
#define LEN   48000
#define NW    64
#define LWT   512
#define BL    (BATCH * LEN)          // 768000

#define INCF  0.032f                 // f32(512/16000)

#define NR0   3000                   // LEN/16
#define NR1   188                    // ceil(3000/16)
#define NR2   12                     // ceil(188/16)

__device__ float g_sums0[BATCH][NR0];   // level-0 row sums
__device__ float g_E1[BATCH][NR0];      // exclusive offsets for level-0 rows
__device__ float g_index[BL];           // final index per element

// ---------------------------------------------------------------------------
// K1: per-16-row sequential folds of increments -> row sums
// ---------------------------------------------------------------------------
__global__ __launch_bounds__(256, 4)
void k1_rowsums(const float* __restrict__ pitch)
{
    int t = blockIdx.x * blockDim.x + threadIdx.x;
    if (t >= BATCH * NR0) return;
    int b = t / NR0;
    int r = t - b * NR0;
    const float4* __restrict__ p4 =
        (const float4*)(pitch + b * LEN + r * 16);

    float acc = 0.0f;
#pragma unroll
    for (int q = 0; q < 4; q++) {
        float4 v = p4[q];
        acc = __fadd_rn(acc, __fmul_rn(INCF, v.x));
        acc = __fadd_rn(acc, __fmul_rn(INCF, v.y));
        acc = __fadd_rn(acc, __fmul_rn(INCF, v.z));
        acc = __fadd_rn(acc, __fmul_rn(INCF, v.w));
    }
    g_sums0[b][r] = acc;
}

// ---------------------------------------------------------------------------
// K2: per-batch level pyramid over the 3000 row sums (one block per batch)
// ---------------------------------------------------------------------------
__global__ __launch_bounds__(256, 1)
void k2_pyramid()
{
    __shared__ float s0[NR0];          // level-1 input (row sums)
    __shared__ float in1[NR1 * 16];    // level-1 inner prefixes (3008)
    __shared__ float in2[NR2 * 16];    // level-2 inner prefixes (192)
    __shared__ float S3[NR2];          // level-3 inclusive scan (12)
    __shared__ float S2[NR1];          // level-2 inclusive values (188)

    const int b = blockIdx.x;
    const int t = threadIdx.x;

    for (int i = t; i < NR0; i += 256) s0[i] = g_sums0[b][i];
    __syncthreads();

    // level-1 inner folds: 188 rows of 16 (pad zeros beyond 3000)
    if (t < NR1) {
        float acc = 0.0f;
        for (int k = 0; k < 16; k++) {
            int idx = t * 16 + k;
            float v = (idx < NR0) ? s0[idx] : 0.0f;
            acc = __fadd_rn(acc, v);
            in1[t * 16 + k] = acc;
        }
    }
    __syncthreads();

    // level-2 inner folds: 12 rows of 16 over the 188 level-1 sums (pad zeros)
    if (t < NR2) {
        float acc = 0.0f;
        for (int k = 0; k < 16; k++) {
            int m = t * 16 + k;
            float v = (m < NR1) ? in1[m * 16 + 15] : 0.0f;
            acc = __fadd_rn(acc, v);
            in2[t * 16 + k] = acc;
        }
    }
    __syncthreads();

    // level-3 direct sequential scan of the 12 level-2 sums
    if (t == 0) {
        float run = 0.0f;
        for (int r = 0; r < NR2; r++) {
            run = __fadd_rn(run, in2[r * 16 + 15]);
            S3[r] = run;
        }
    }
    __syncthreads();

    // level-2 inclusive values: S2[m] = in2[m] + E3[m>>4]
    if (t < NR1) {
        int q = t >> 4;
        float e3 = (q == 0) ? 0.0f : S3[q - 1];
        S2[t] = __fadd_rn(in2[t], e3);
    }
    __syncthreads();

    // level-1 exclusive offsets for level-0 rows:
    // E1[r] = S1[r-1],  S1[m] = in1[m] + E2[m>>4],  E2[q] = S2[q-1]
    for (int r = t; r < NR0; r += 256) {
        float e1;
        if (r == 0) {
            e1 = 0.0f;
        } else {
            int m = r - 1;
            int q = m >> 4;
            float e2 = (q == 0) ? 0.0f : S2[q - 1];
            e1 = __fadd_rn(in1[m], e2);
        }
        g_E1[b][r] = e1;
    }
}

// ---------------------------------------------------------------------------
// K3: emit final index. One thread per level-0 row (16 elements each).
// ---------------------------------------------------------------------------
__global__ __launch_bounds__(128, 8)
void k3_index(const float* __restrict__ pitch)
{
    int t = blockIdx.x * blockDim.x + threadIdx.x;
    if (t >= BATCH * NR0) return;
    int b = t / NR0;
    int r = t - b * NR0;

    const float4* __restrict__ pb = (const float4*)(pitch + b * LEN + r * 16);
    const float4* __restrict__ p0 = (const float4*)(pitch + r * 16);
    float4* __restrict__ o4 = (float4*)(g_index + b * LEN + r * 16);

    const float e1 = g_E1[b][r];
    float acc = 0.0f;
#pragma unroll
    for (int q = 0; q < 4; q++) {
        float4 v = pb[q];
        float4 z = p0[q];
        float out[4];
        float vv[4] = {v.x, v.y, v.z, v.w};
        float zz[4] = {z.x, z.y, z.z, z.w};
#pragma unroll
        for (int k = 0; k < 4; k++) {
            acc = __fadd_rn(acc, __fmul_rn(INCF, vv[k]));
            float S0 = __fadd_rn(acc, e1);
            float x  = __fsub_rn(S0, __fmul_rn(INCF, zz[k]));
            float rr = fmodf(x, 512.0f);
            if (rr < 0.0f) rr = __fadd_rn(rr, 512.0f);
            if (__fsub_rn(512.0f, rr) < 1e-5f) rr = 0.0f;
            out[k] = rr;
        }
        o4[q] = make_float4(out[0], out[1], out[2], out[3]);
    }
}

// ---------------------------------------------------------------------------
// Synth: HALF-WARP per element. Lanes 0-15 -> element 2p, lanes 16-31 -> 2p+1.
// Each lane covers 4 wavetables via float4 LDS (layout [pos][64]).
// 4 shfl_xor (8,4,2,1) reduce both halves simultaneously.
// ---------------------------------------------------------------------------
#define SYNTH_SMEM_BYTES (LWT * NW * 4)   // 131072
#define NPAIRS (BL / 2)                   // 384000

__device__ __forceinline__ float synth_pair_lane(
    float r, float4 a, const float4* __restrict__ wt4, int hl)
{
    float fl = floorf(r);
    int   il = (int)fl;
    float al = r - fl;
    int   ih = (int)ceilf(r);
    if (ih >= LWT) ih = 0;
    float4 lo = wt4[(il << 4) + hl];
    float4 hi = wt4[(ih << 4) + hl];
    float w0 = lo.x + al * (hi.x - lo.x);
    float w1 = lo.y + al * (hi.y - lo.y);
    float w2 = lo.z + al * (hi.z - lo.z);
    float w3 = lo.w + al * (hi.w - lo.w);
    float v = w0 * a.x;
    v = fmaf(w1, a.y, v);
    v = fmaf(w2, a.z, v);
    v = fmaf(w3, a.w, v);
    return v;
}

__device__ __forceinline__ float half_sum(float v)
{
#pragma unroll
    for (int off = 8; off > 0; off >>= 1)
        v += __shfl_xor_sync(0xffffffffu, v, off);
    return v;
}

__global__ __launch_bounds__(1024, 1)
void synth_kernel(const float* __restrict__ env,
                  const float* __restrict__ att,
                  const float* __restrict__ wtab,
                  float* __restrict__ out)
{
    extern __shared__ float wt[];   // [512][64] transposed
    for (int i = threadIdx.x; i < NW * LWT; i += 1024) {
        int w = i >> 9;
        int j = i & (LWT - 1);
        wt[j * NW + w] = wtab[i];
    }
    __syncthreads();

    const float4* __restrict__ wt4  = (const float4*)wt;
    const float4* __restrict__ att4 = (const float4*)att;

    const int lane = threadIdx.x & 31;
    const int half = lane >> 4;             // 0 or 1
    const int hl   = lane & 15;             // half-lane 0..15
    const int warp = (blockIdx.x << 5) + (threadIdx.x >> 5);
    const int nw   = gridDim.x << 5;

    int p = warp;
    for (; p + 3 * nw < NPAIRS; p += 4 * nw) {
        int me0 = 2 * p + half;
        int me1 = 2 * (p + nw) + half;
        int me2 = 2 * (p + 2 * nw) + half;
        int me3 = 2 * (p + 3 * nw) + half;

        float r0 = __ldg(&g_index[me0]);
        float r1 = __ldg(&g_index[me1]);
        float r2 = __ldg(&g_index[me2]);
        float r3 = __ldg(&g_index[me3]);
        float4 a0 = att4[me0 * 16 + hl];
        float4 a1 = att4[me1 * 16 + hl];
        float4 a2 = att4[me2 * 16 + hl];
        float4 a3 = att4[me3 * 16 + hl];
        float ev0 = __ldg(&env[me0]);
        float ev1 = __ldg(&env[me1]);
        float ev2 = __ldg(&env[me2]);
        float ev3 = __ldg(&env[me3]);

        float v0 = synth_pair_lane(r0, a0, wt4, hl);
        float v1 = synth_pair_lane(r1, a1, wt4, hl);
        float v2 = synth_pair_lane(r2, a2, wt4, hl);
        float v3 = synth_pair_lane(r3, a3, wt4, hl);

        v0 = half_sum(v0);
        v1 = half_sum(v1);
        v2 = half_sum(v2);
        v3 = half_sum(v3);

        if (hl == 0) {
            out[me0] = v0 * ev0;
            out[me1] = v1 * ev1;
            out[me2] = v2 * ev2;
            out[me3] = v3 * ev3;
        }
    }
    for (; p < NPAIRS; p += nw) {
        int me = 2 * p + half;
        float r  = __ldg(&g_index[me]);
        float4 a = att4[me * 16 + hl];
        float ev = __ldg(&env[me]);
        float v = half_sum(synth_pair_lane(r, a, wt4, hl));
        if (hl == 0) out[me] = v * ev;
    }
}

// ---------------------------------------------------------------------------
extern "C" void kernel_launch(void* const* d_in, const int* in_sizes, int n_in,
                              void* d_out, int out_size)
{
    const float* pitch = (const float*)d_in[0];
    const float* env   = (const float*)d_in[1];
    const float* att   = (const float*)d_in[2];
    const float* wtab  = (const float*)d_in[3];
    float* out = (float*)d_out;

    cudaFuncSetAttribute(synth_kernel,
        cudaFuncAttributeMaxDynamicSharedMemorySize, SYNTH_SMEM_BYTES);

    int nsm = 148;
    cudaDeviceGetAttribute(&nsm, cudaDevAttrMultiProcessorCount, 0);

    k1_rowsums<<<(BATCH * NR0 + 255) / 256, 256>>>(pitch);
    k2_pyramid<<<BATCH, 256>>>();
    k3_index<<<(BATCH * NR0 + 127) / 128, 128>>>(pitch);
    synth_kernel<<<nsm, 1024, SYNTH_SMEM_BYTES>>>(env, att, wtab, out);
}